// round 14
// baseline (speedup 1.0000x reference)
#include <cuda_runtime.h>
#include <math.h>

#define BATCH 64
#define SEQ   512
#define EMBED 256
#define HID   512
#define GD    768     // HID + EMBED
#define NCLS  4

#define NBLK  128     // 2 batch halves x 64 column groups
#define NTHR  256     // 8 warps
#define BG    32      // batch rows per CTA (two pipelined sub-halves of 16)
#define ND    32      // dot-columns per CTA = 4 gates * 8 hidden units
#define K4T   192     // GD / 4
#define HALF_CTAS 64

// SMEM: w[32][768] + inp[32][768] (A rows 0-15, B rows 16-31) + 8 partial sets + bias
#define SM_W       0
#define SM_INP     (32*768)
#define SM_PART    (SM_INP + 32*768)
#define SET_STRIDE 544                  // 32 cols' x 17 (16-row padded)
#define SM_BIAS    (SM_PART + 8*SET_STRIDE)
#define SMEM_FLOATS (SM_BIAS + 32)
#define SMEM_BYTES  (SMEM_FLOATS * 4)   // 214,144 B

__device__ float g_h[2][BATCH*HID];
__device__ float g_maxh[BATCH*HID];
__device__ unsigned long long g_cnt;          // full-grid ticket counter
__device__ unsigned long long g_bar[4*32];    // 4 group counters, 256B apart

__device__ __forceinline__ float sigf(float x)     { return 1.0f / (1.0f + __expf(-x)); }
__device__ __forceinline__ float tanhfast(float x) { return 2.0f / (1.0f + __expf(-2.0f*x)) - 1.0f; }

__device__ __forceinline__ void fma2(unsigned long long &d,
                                     unsigned long long a, unsigned long long b) {
    asm("fma.rn.f32x2 %0, %1, %2, %0;" : "+l"(d) : "l"(a), "l"(b));
}
__device__ __forceinline__ float sum2(unsigned long long v) {
    float lo, hi;
    asm("mov.b64 {%0,%1}, %2;" : "=f"(lo), "=f"(hi) : "l"(v));
    return lo + hi;
}

__device__ __forceinline__ void cp16_cg(unsigned int saddr, const void* g) {
    asm volatile("cp.async.cg.shared.global [%0], [%1], 16;" :: "r"(saddr), "l"(g));
}
#define CP_COMMIT()   asm volatile("cp.async.commit_group;" ::: "memory")
#define CP_WAITALL()  asm volatile("cp.async.wait_all;"     ::: "memory")
#define CP_WAIT_ONE() asm volatile("cp.async.wait_group 1;" ::: "memory")

// Full-grid ticket barrier (fence-free; init and finish only).
__device__ __forceinline__ void ticket_barrier() {
    __syncthreads();
    if (threadIdx.x == 0) {
        unsigned long long ticket;
        asm volatile("atom.release.gpu.add.u64 %0, [%1], %2;"
                     : "=l"(ticket) : "l"(&g_cnt), "l"(1ULL) : "memory");
        unsigned long long target = (ticket / NBLK + 1ULL) * (unsigned long long)NBLK;
        unsigned long long cur;
        do {
            asm volatile("ld.acquire.gpu.u64 %0, [%1];"
                         : "=l"(cur) : "l"(&g_cnt) : "memory");
        } while (cur < target);
    }
    __syncthreads();
}

__device__ __forceinline__ void arrive(unsigned long long* ctr) {
    asm volatile("red.release.gpu.add.u64 [%0], %1;" :: "l"(ctr), "l"(1ULL) : "memory");
}
__device__ __forceinline__ void poll(unsigned long long* ctr, unsigned long long target) {
    unsigned long long cur;
    do {
        asm volatile("ld.acquire.gpu.u64 %0, [%1];" : "=l"(cur) : "l"(ctr) : "memory");
    } while (cur < target);
}

// 16-row x 32-col GEMM over a sub-half: 4x8 lane tile, 16-way K split, shfl fold.
__device__ __forceinline__ void gemm_sub(const float* xr0, const float* wc0, float* pbase,
                                         int kb, int rg, int s0, int s1, int lh) {
    unsigned long long acc[4][8];
    #pragma unroll
    for (int r = 0; r < 4; r++)
        #pragma unroll
        for (int c = 0; c < 8; c++) acc[r][c] = 0ULL;

    #pragma unroll 4
    for (int kk = 0; kk < 12; kk++) {
        int k4 = kb + kk;
        int ox = ((k4 ^ rg) << 2);
        int o0 = ((k4 ^ s0) << 2), o1 = ((k4 ^ s1) << 2);
        ulonglong2 xv[4], wv[8];
        #pragma unroll
        for (int r = 0; r < 4; r++)
            xv[r] = *(const ulonglong2*)(xr0 + r*GD + ox);
        #pragma unroll
        for (int c = 0; c < 8; c++)
            wv[c] = *(const ulonglong2*)(wc0 + c*GD + (c < 4 ? o0 : o1));
        #pragma unroll
        for (int c = 0; c < 8; c++)
            #pragma unroll
            for (int r = 0; r < 4; r++) {
                fma2(acc[r][c], xv[r].x, wv[c].x);
                fma2(acc[r][c], xv[r].y, wv[c].y);
            }
    }
    // fold lh halves (lane i += lane i+16) + scalar store (conflict-free, 17-stride)
    #pragma unroll
    for (int c = 0; c < 8; c++) {
        float v[4];
        #pragma unroll
        for (int r = 0; r < 4; r++) {
            v[r] = sum2(acc[r][c]);
            v[r] += __shfl_down_sync(0xffffffffu, v[r], 16);
        }
        if (lh == 0) {
            #pragma unroll
            for (int r = 0; r < 4; r++) pbase[c*68 + r] = v[r];
        }
    }
}

extern "C" __global__ void __launch_bounds__(NTHR, 1)
lstm_persistent(const int*   __restrict__ ids,
                const float* __restrict__ emb,
                const float* __restrict__ Wf, const float* __restrict__ bf,
                const float* __restrict__ Wi, const float* __restrict__ bi,
                const float* __restrict__ Wo, const float* __restrict__ bo,
                const float* __restrict__ Wc, const float* __restrict__ bc,
                const float* __restrict__ fcw, const float* __restrict__ fcb,
                float* __restrict__ out)
{
    extern __shared__ float sm[];
    float* w_s    = sm + SM_W;
    float* inpA   = sm + SM_INP;            // rows 0..15
    float* inpB   = sm + SM_INP + 16*GD;    // rows 16..31
    float* part_s = sm + SM_PART;
    float* bias_s = sm + SM_BIAS;

    const int tid  = threadIdx.x;
    const int cta  = blockIdx.x;
    const int half = cta & 1;
    const int b0   = half * BG;
    const int j0   = (cta >> 1) * 8;
    const int wid  = tid >> 5;
    const int lane = tid & 31;

    unsigned long long* ctrA = &g_bar[(half*2 + 0) * 32];
    unsigned long long* ctrB = &g_bar[(half*2 + 1) * 32];

    const float* Wg[4]  = {Wf, Wi, Wo, Wc};
    const float* bgp[4] = {bf, bi, bo, bc};

    // ---- one-time: weight slice into swizzled SMEM (key (d>>2)&7) ----
    for (int idx = tid; idx < ND*K4T; idx += NTHR) {
        int d  = idx / K4T;
        int k4 = idx - d*K4T;
        int g  = d >> 3, jj = d & 7;
        float4 v = ((const float4*)(Wg[g] + (size_t)(j0 + jj) * GD))[k4];
        *(float4*)(w_s + d*GD + ((k4 ^ ((d >> 2) & 7)) << 2)) = v;
    }
    if (tid < ND) {
        int g = tid >> 3, jj = tid & 7;
        bias_s[tid] = bgp[g][j0 + jj];
    }
    if (tid < BG*8) {                       // zero h(0) region this CTA owns
        int r = tid >> 3, jj = tid & 7;
        g_h[0][(b0 + r)*HID + j0 + jj] = 0.0f;
    }

    // GEMM mapping: 8 warps, 16 K-segments (2 per warp via lane halves)
    const int lh = lane >> 4;
    const int li = lane & 15;
    const int rg = li >> 2;                  // rows 4rg..4rg+3 of the sub-buffer
    const int cg = li & 3;                   // cols 8cg..8cg+7
    const int kb = (wid*2 + lh) * 12;
    const int s0 = 2*cg, s1 = 2*cg + 1;
    const float* xr0A = inpA + (4*rg) * GD;
    const float* xr0B = inpB + (4*rg) * GD;
    const float* wc0  = w_s  + (8*cg) * GD;
    float* pbase = part_s + wid*SET_STRIDE + cg*17 + 4*rg;

    // staging mapping: warp stages sub-rows {2wid, 2wid+1}, lane covers 16 k4
    const int sdr  = lane >> 4;              // 0..1
    const int sdk  = lane & 15;              // 0..15
    const int srow = 2*wid + sdr;            // 0..15
    const int skey = srow >> 2;
    const unsigned int sdstA = (unsigned int)__cvta_generic_to_shared(inpA + srow*GD);
    const unsigned int sdstB = (unsigned int)__cvta_generic_to_shared(inpB + srow*GD);
    const int growA = b0 + srow;
    const int growB = b0 + 16 + srow;

    // epilogue mapping (tid < 128): one (sub-row, unit) per thread, both subs
    const int eb  = (tid & 127) >> 3;        // 0..15
    const int ejj = tid & 7;

    float cstA = 0.0f, cstB = 0.0f;
    float mmaxA = -INFINITY, mmaxB = -INFINITY;

    unsigned long long baseA = *((volatile unsigned long long*)ctrA);
    unsigned long long baseB = *((volatile unsigned long long*)ctrB);

    ticket_barrier();                        // h(0), bases settled

    // ---- prologue staging: A(0) then B(0) (h=0 rows + emb t=0) ----
    {
        const float4* hrow = (const float4*)(g_h[0] + (size_t)growA * HID);
        #pragma unroll
        for (int o = 0; o < 8; o++) { int k4 = o*16 + sdk; cp16_cg(sdstA + ((k4^skey)<<4), hrow + k4); }
        const float4* erow = (const float4*)(emb + (size_t)__ldg(ids + growA*SEQ) * EMBED);
        #pragma unroll
        for (int o = 0; o < 4; o++) { int k4 = 128 + o*16 + sdk; cp16_cg(sdstA + ((k4^skey)<<4), erow + o*16 + sdk); }
        CP_COMMIT();
    }
    {
        const float4* hrow = (const float4*)(g_h[0] + (size_t)growB * HID);
        #pragma unroll
        for (int o = 0; o < 8; o++) { int k4 = o*16 + sdk; cp16_cg(sdstB + ((k4^skey)<<4), hrow + k4); }
        const float4* erow = (const float4*)(emb + (size_t)__ldg(ids + growB*SEQ) * EMBED);
        #pragma unroll
        for (int o = 0; o < 4; o++) { int k4 = 128 + o*16 + sdk; cp16_cg(sdstB + ((k4^skey)<<4), erow + o*16 + sdk); }
        CP_COMMIT();
    }

    for (int t = 0; t < SEQ; t++) {
        float* hnext = g_h[(t + 1) & 1];

        // ======== A phase ========
        CP_WAIT_ONE();                       // A(t) staged (B group may be in flight)
        __syncthreads();
        gemm_sub(xr0A, wc0, pbase, kb, rg, s0, s1, lh);
        __syncthreads();
        if (tid < 128) {
            float pf = bias_s[ 0 + ejj], pi = bias_s[ 8 + ejj];
            float po = bias_s[16 + ejj], pg = bias_s[24 + ejj];
            #pragma unroll
            for (int s = 0; s < 8; s++) {
                const float* sp = part_s + s*SET_STRIDE + eb;
                pf += sp[(4*ejj + 0)*17]; pi += sp[(4*ejj + 1)*17];
                po += sp[(4*ejj + 2)*17]; pg += sp[(4*ejj + 3)*17];
            }
            float f = sigf(pf), iv = sigf(pi), o = sigf(po), gg = tanhfast(pg);
            cstA = f*cstA + iv*gg;
            float h = o * tanhfast(cstA);
            mmaxA = fmaxf(mmaxA, h);
            hnext[(size_t)(b0 + eb)*HID + j0 + ejj] = h;
        }
        __syncthreads();
        if (tid == 0) arrive(ctrA);

        // ======== B phase (barA completes underneath) ========
        CP_WAITALL();                        // B(t) staged
        __syncthreads();
        gemm_sub(xr0B, wc0, pbase, kb, rg, s0, s1, lh);
        __syncthreads();
        if (tid < 128) {
            float pf = bias_s[ 0 + ejj], pi = bias_s[ 8 + ejj];
            float po = bias_s[16 + ejj], pg = bias_s[24 + ejj];
            #pragma unroll
            for (int s = 0; s < 8; s++) {
                const float* sp = part_s + s*SET_STRIDE + eb;
                pf += sp[(4*ejj + 0)*17]; pi += sp[(4*ejj + 1)*17];
                po += sp[(4*ejj + 2)*17]; pg += sp[(4*ejj + 3)*17];
            }
            float f = sigf(pf), iv = sigf(pi), o = sigf(po), gg = tanhfast(pg);
            cstB = f*cstB + iv*gg;
            float h = o * tanhfast(cstB);
            mmaxB = fmaxf(mmaxB, h);
            hnext[(size_t)(b0 + 16 + eb)*HID + j0 + ejj] = h;
        }
        __syncthreads();
        if (tid == 0) arrive(ctrB);

        // ======== prep t+1: polls hidden by the other phase / staging flight ========
        if (t + 1 < SEQ) {
            if (tid == 0) poll(ctrA, baseA + (unsigned long long)HALF_CTAS * (t + 1));
            __syncthreads();
            {   // stage A(t+1)
                const float4* hrow = (const float4*)(hnext + (size_t)growA * HID);
                #pragma unroll
                for (int o = 0; o < 8; o++) { int k4 = o*16 + sdk; cp16_cg(sdstA + ((k4^skey)<<4), hrow + k4); }
                const float4* erow = (const float4*)(emb + (size_t)__ldg(ids + growA*SEQ + t + 1) * EMBED);
                #pragma unroll
                for (int o = 0; o < 4; o++) { int k4 = 128 + o*16 + sdk; cp16_cg(sdstA + ((k4^skey)<<4), erow + o*16 + sdk); }
                CP_COMMIT();
            }
            if (tid == 0) poll(ctrB, baseB + (unsigned long long)HALF_CTAS * (t + 1));
            __syncthreads();
            {   // stage B(t+1)
                const float4* hrow = (const float4*)(hnext + (size_t)growB * HID);
                #pragma unroll
                for (int o = 0; o < 8; o++) { int k4 = o*16 + sdk; cp16_cg(sdstB + ((k4^skey)<<4), hrow + k4); }
                const float4* erow = (const float4*)(emb + (size_t)__ldg(ids + growB*SEQ + t + 1) * EMBED);
                #pragma unroll
                for (int o = 0; o < 4; o++) { int k4 = 128 + o*16 + sdk; cp16_cg(sdstB + ((k4^skey)<<4), erow + o*16 + sdk); }
                CP_COMMIT();
            }
        }
    }

    // ---- max-over-time out, then tiny FC on CTA 0 ----
    if (tid < 128) {
        g_maxh[(size_t)(b0 + eb)*HID + j0 + ejj]      = mmaxA;
        g_maxh[(size_t)(b0 + 16 + eb)*HID + j0 + ejj] = mmaxB;
    }
    ticket_barrier();

    if (cta == 0) {
        int b  = tid >> 2;
        int ci = tid & 3;
        const float4* a4 = (const float4*)(g_maxh + (size_t)b * HID);
        const float4* w4 = (const float4*)(fcw + (size_t)ci * HID);
        float acc0 = fcb[ci];
        #pragma unroll 4
        for (int k = 0; k < HID/4; k++) {
            float4 a = __ldcg(a4 + k);
            float4 w = w4[k];
            acc0 += a.x*w.x + a.y*w.y + a.z*w.z + a.w*w.w;
        }
        out[b*NCLS + ci] = acc0;
    }
}

extern "C" void kernel_launch(void* const* d_in, const int* in_sizes, int n_in,
                              void* d_out, int out_size)
{
    const int*   ids = (const int*)  d_in[0];
    const float* emb = (const float*)d_in[1];
    const float* Wf  = (const float*)d_in[2];
    const float* bf  = (const float*)d_in[3];
    const float* Wi  = (const float*)d_in[4];
    const float* bi  = (const float*)d_in[5];
    const float* Wo  = (const float*)d_in[6];
    const float* bo  = (const float*)d_in[7];
    const float* Wc  = (const float*)d_in[8];
    const float* bc  = (const float*)d_in[9];
    const float* fcw = (const float*)d_in[10];
    const float* fcb = (const float*)d_in[11];
    float* out = (float*)d_out;

    cudaFuncSetAttribute(lstm_persistent,
                         cudaFuncAttributeMaxDynamicSharedMemorySize, SMEM_BYTES);
    lstm_persistent<<<NBLK, NTHR, SMEM_BYTES>>>(ids, emb, Wf, bf, Wi, bi,
                                                Wo, bo, Wc, bc, fcw, fcb, out);
}

// round 15
// speedup vs baseline: 1.1356x; 1.1356x over previous
#include <cuda_runtime.h>
#include <math.h>

#define BATCH 64
#define SEQ   512
#define EMBED 256
#define HID   512
#define GD    768     // HID + EMBED
#define NCLS  4

#define NBLK  128     // 2 batch halves x 64 column groups
#define NTHR  512     // 16 warps = 4 per SMSP
#define BG    32      // batch rows per CTA
#define ND    32      // dot-columns per CTA
#define K4T   192     // GD / 4
#define HALF_CTAS 64

// SMEM: w[32][768] + inp[32][768] + 4 static partial sets + bias.
// Partial sets 0..11 live in the inp h-region (dead between GEMM end and
// next h staging); sets 12..15 in the static area.
#define SM_W       0
#define SM_INP     (32*768)
#define SM_PARTR   (SM_INP + 32*768)
#define SET_STRIDE 1056                 // 32 cols' x 33 (row-padded)
#define SM_BIAS    (SM_PARTR + 4*SET_STRIDE)
#define SMEM_FLOATS (SM_BIAS + 32)
#define SMEM_BYTES  (SMEM_FLOATS * 4)   // 213,760 B

__device__ float g_h[2][BATCH*HID];
__device__ float g_maxh[BATCH*HID];
__device__ unsigned long long g_cnt;          // full-grid ticket counter
__device__ unsigned long long g_half[64];     // per-half counters (slots 0, 32)

__device__ __forceinline__ float sigf(float x)     { return 1.0f / (1.0f + __expf(-x)); }
__device__ __forceinline__ float tanhfast(float x) { return 2.0f / (1.0f + __expf(-2.0f*x)) - 1.0f; }

__device__ __forceinline__ void fma2(unsigned long long &d,
                                     unsigned long long a, unsigned long long b) {
    asm("fma.rn.f32x2 %0, %1, %2, %0;" : "+l"(d) : "l"(a), "l"(b));
}
__device__ __forceinline__ float sum2(unsigned long long v) {
    float lo, hi;
    asm("mov.b64 {%0,%1}, %2;" : "=f"(lo), "=f"(hi) : "l"(v));
    return lo + hi;
}

__device__ __forceinline__ void cp16_cg(unsigned int saddr, const void* g) {
    asm volatile("cp.async.cg.shared.global [%0], [%1], 16;" :: "r"(saddr), "l"(g));
}
#define CP_COMMIT()  asm volatile("cp.async.commit_group;" ::: "memory")
#define CP_WAITALL() asm volatile("cp.async.wait_all;"     ::: "memory")

// Full-grid ticket barrier (fence-free; init and finish only).
__device__ __forceinline__ void ticket_barrier() {
    __syncthreads();
    if (threadIdx.x == 0) {
        unsigned long long ticket;
        asm volatile("atom.release.gpu.add.u64 %0, [%1], %2;"
                     : "=l"(ticket) : "l"(&g_cnt), "l"(1ULL) : "memory");
        unsigned long long target = (ticket / NBLK + 1ULL) * (unsigned long long)NBLK;
        unsigned long long cur;
        do {
            asm volatile("ld.acquire.gpu.u64 %0, [%1];"
                         : "=l"(cur) : "l"(&g_cnt) : "memory");
        } while (cur < target);
    }
    __syncthreads();
}

extern "C" __global__ void __launch_bounds__(NTHR, 1)
lstm_persistent(const int*   __restrict__ ids,
                const float* __restrict__ emb,
                const float* __restrict__ Wf, const float* __restrict__ bf,
                const float* __restrict__ Wi, const float* __restrict__ bi,
                const float* __restrict__ Wo, const float* __restrict__ bo,
                const float* __restrict__ Wc, const float* __restrict__ bc,
                const float* __restrict__ fcw, const float* __restrict__ fcb,
                float* __restrict__ out)
{
    extern __shared__ float sm[];
    float* w_s    = sm + SM_W;
    float* inp_s  = sm + SM_INP;
    float* partr  = sm + SM_PARTR;
    float* bias_s = sm + SM_BIAS;

    const int tid  = threadIdx.x;
    const int cta  = blockIdx.x;
    const int half = cta & 1;
    const int b0   = half * BG;
    const int j0   = (cta >> 1) * 8;
    const int wid  = tid >> 5;              // 0..15
    const int lane = tid & 31;

    unsigned long long* hctr = &g_half[half * 32];

    const float* Wg[4]  = {Wf, Wi, Wo, Wc};
    const float* bgp[4] = {bf, bi, bo, bc};

    // ---- one-time: weight slice into swizzled SMEM (key (d>>2)&7) ----
    for (int idx = tid; idx < ND*K4T; idx += NTHR) {
        int d  = idx / K4T;
        int k4 = idx - d*K4T;
        int g  = d >> 3, jj = d & 7;
        float4 v = ((const float4*)(Wg[g] + (size_t)(j0 + jj) * GD))[k4];
        *(float4*)(w_s + d*GD + ((k4 ^ ((d >> 2) & 7)) << 2)) = v;
    }
    if (tid < ND) {
        int g = tid >> 3, jj = tid & 7;
        bias_s[tid] = bgp[g][j0 + jj];
    }
    if (tid < BG*8) {                       // zero h(0) region this CTA owns
        int r = tid >> 3, jj = tid & 7;
        g_h[0][(b0 + r)*HID + j0 + jj] = 0.0f;
    }

    // GEMM mapping: each warp covers full 32x32 tile, K split 16 ways
    const int rg = lane >> 2;                // rows 4rg..4rg+3 (x key = rg)
    const int cg = lane & 3;                 // cols 8cg..8cg+7
    const int kb = wid * 12;                 // 16 segments x 12 k4
    const int s0 = 2*cg;                     // w key, cols 8cg..8cg+3
    const int s1 = 2*cg + 1;                 // w key, cols 8cg+4..8cg+7
    const float* xr0 = inp_s + (4*rg) * GD;
    const float* wc0 = w_s   + (8*cg) * GD;

    // partial set base for this warp (sets 0..11 in inp h-region, 12..15 static)
    float* myset = (wid < 12) ? (inp_s + wid*SET_STRIDE)
                              : (partr + (wid - 12)*SET_STRIDE);

    // staging mapping: warp stages rows {2wid, 2wid+1}; lane covers 16-k4 strip
    const int sdr  = lane >> 4;               // 0..1
    const int sdk  = lane & 15;               // 0..15
    const int srow = 2*wid + sdr;             // 0..31
    const int skey = srow >> 2;
    float* sdst = inp_s + srow * GD;
    const unsigned int sdst_s = (unsigned int)__cvta_generic_to_shared(sdst);
    const int* idrow = ids + (b0 + srow)*SEQ;

    // epilogue mapping (tid < 256): one thread per (batch row, hidden unit)
    const int eb  = (tid & 255) >> 3;          // 0..31
    const int ejj = tid & 7;                   // 0..7
    const bool epi = (tid < 256);

    float cst  = 0.0f;
    float mmax = -INFINITY;

    // ---- pre-stage embedding for t=0 (plain stores) ----
    {
        int id0 = __ldg(idrow + 0);
        const float4* erow = (const float4*)(emb + (size_t)id0 * EMBED);
        #pragma unroll
        for (int o = 0; o < 4; o++) {
            int k4 = 128 + o*16 + sdk;
            *(float4*)(sdst + ((k4 ^ skey) << 2)) = erow[o*16 + sdk];
        }
    }

    unsigned long long hbase = *((volatile unsigned long long*)hctr);

    ticket_barrier();                           // h(0), emb(0), hbase settled

    for (int t = 0; t < SEQ; t++) {
        // ---- 1. stage h(t) via cp.async (.cg = L2-direct) ----
        {
            const float4* hrow = (const float4*)(g_h[t & 1] + (size_t)(b0 + srow) * HID);
            #pragma unroll
            for (int o = 0; o < 8; o++) {
                int k4 = o*16 + sdk;
                cp16_cg(sdst_s + ((k4 ^ skey) << 4), hrow + k4);
            }
            CP_COMMIT();
        }
        CP_WAITALL();                           // h(t) + emb(t, issued last step)
        __syncthreads();

        // ---- 2. GEMM: 4x8 lane tile, 12 k4, x batched / w streamed ----
        unsigned long long acc[4][8];
        #pragma unroll
        for (int r = 0; r < 4; r++)
            #pragma unroll
            for (int c = 0; c < 8; c++) acc[r][c] = 0ULL;

        #pragma unroll 2
        for (int kk = 0; kk < 12; kk++) {
            int k4 = kb + kk;
            int ox = ((k4 ^ rg) << 2);
            int o0 = ((k4 ^ s0) << 2), o1 = ((k4 ^ s1) << 2);
            ulonglong2 xv[4];
            #pragma unroll
            for (int r = 0; r < 4; r++)
                xv[r] = *(const ulonglong2*)(xr0 + r*GD + ox);
            #pragma unroll
            for (int c = 0; c < 8; c++) {
                ulonglong2 wv = *(const ulonglong2*)(wc0 + c*GD + (c < 4 ? o0 : o1));
                #pragma unroll
                for (int r = 0; r < 4; r++) {
                    fma2(acc[r][c], xv[r].x, wv.x);
                    fma2(acc[r][c], xv[r].y, wv.y);
                }
            }
        }
        __syncthreads();                        // all x reads done (h-region now dead)

        // ---- 3. partial store (scalar, conflict-free 33-stride) ----
        #pragma unroll
        for (int c = 0; c < 8; c++)
            #pragma unroll
            for (int r = 0; r < 4; r++)
                myset[(4*c + cg)*33 + 4*rg + r] = sum2(acc[r][c]);
        __syncthreads();

        // ---- 4. epilogue: sum 16 segments, gates, state update, h store ----
        if (epi) {
            float pf = bias_s[ 0 + ejj];
            float pi = bias_s[ 8 + ejj];
            float po = bias_s[16 + ejj];
            float pg = bias_s[24 + ejj];
            #pragma unroll
            for (int s = 0; s < 16; s++) {
                const float* sp = ((s < 12) ? (inp_s + s*SET_STRIDE)
                                            : (partr + (s - 12)*SET_STRIDE)) + eb;
                pf += sp[(4*ejj + 0)*33];
                pi += sp[(4*ejj + 1)*33];
                po += sp[(4*ejj + 2)*33];
                pg += sp[(4*ejj + 3)*33];
            }
            float f  = sigf(pf);
            float iv = sigf(pi);
            float o  = sigf(po);
            float gg = tanhfast(pg);
            cst = f*cst + iv*gg;
            float h = o * tanhfast(cst);
            mmax = fmaxf(mmax, h);
            g_h[(t + 1) & 1][(size_t)(b0 + eb)*HID + j0 + ejj] = h;
        }
        __syncthreads();                        // partial reads + h stores done

        // ---- 5. arrive; emb(t+1) prefetch (partials dead now); poll ----
        if (t + 1 < SEQ) {
            if (tid == 0)
                asm volatile("red.release.gpu.add.u64 [%0], %1;"
                             :: "l"(hctr), "l"(1ULL) : "memory");
            {
                int id1 = __ldg(idrow + t + 1);
                const float4* erow = (const float4*)(emb + (size_t)id1 * EMBED);
                #pragma unroll
                for (int o = 0; o < 4; o++) {
                    int k4 = 128 + o*16 + sdk;
                    cp16_cg(sdst_s + ((k4 ^ skey) << 4), erow + o*16 + sdk);
                }
                CP_COMMIT();
            }
            if (tid == 0) {
                unsigned long long target =
                    hbase + (unsigned long long)HALF_CTAS * (t + 1);
                unsigned long long cur;
                do {
                    asm volatile("ld.acquire.gpu.u64 %0, [%1];"
                                 : "=l"(cur) : "l"(hctr) : "memory");
                } while (cur < target);
            }
            __syncthreads();                    // barrier complete
        }
    }

    // ---- max-over-time out, then tiny FC on CTA 0 ----
    if (epi)
        g_maxh[(size_t)(b0 + eb)*HID + j0 + ejj] = mmax;
    ticket_barrier();

    if (cta == 0 && tid < 256) {
        int b  = tid >> 2;
        int ci = tid & 3;
        const float4* a4 = (const float4*)(g_maxh + (size_t)b * HID);
        const float4* w4 = (const float4*)(fcw + (size_t)ci * HID);
        float acc0 = fcb[ci];
        #pragma unroll 4
        for (int k = 0; k < HID/4; k++) {
            float4 a = __ldcg(a4 + k);
            float4 w = w4[k];
            acc0 += a.x*w.x + a.y*w.y + a.z*w.z + a.w*w.w;
        }
        out[b*NCLS + ci] = acc0;
    }
}

extern "C" void kernel_launch(void* const* d_in, const int* in_sizes, int n_in,
                              void* d_out, int out_size)
{
    const int*   ids = (const int*)  d_in[0];
    const float* emb = (const float*)d_in[1];
    const float* Wf  = (const float*)d_in[2];
    const float* bf  = (const float*)d_in[3];
    const float* Wi  = (const float*)d_in[4];
    const float* bi  = (const float*)d_in[5];
    const float* Wo  = (const float*)d_in[6];
    const float* bo  = (const float*)d_in[7];
    const float* Wc  = (const float*)d_in[8];
    const float* bc  = (const float*)d_in[9];
    const float* fcw = (const float*)d_in[10];
    const float* fcb = (const float*)d_in[11];
    float* out = (float*)d_out;

    cudaFuncSetAttribute(lstm_persistent,
                         cudaFuncAttributeMaxDynamicSharedMemorySize, SMEM_BYTES);
    lstm_persistent<<<NBLK, NTHR, SMEM_BYTES>>>(ids, emb, Wf, bf, Wi, bi,
                                                Wo, bo, Wc, bc, fcw, fcb, out);
}